// round 4
// baseline (speedup 1.0000x reference)
#include <cuda_runtime.h>
#include <cuda_bf16.h>

#define N_NODES  100000
#define N_EDGES  3200000
#define E_TOT    (N_EDGES + N_NODES)   // edges + self loops
#define IN_DIM   128
#define H1F1     64                    // 8 heads x 8 feats
#define NCLS     40
#define NEG_SLOPE 0.2f

// ---------------- scratch (static device globals; 16B-aligned for vec ops) --
static __device__ __align__(16) int   g_src[N_EDGES];
static __device__ __align__(16) int   g_dst[N_EDGES];
static __device__ __align__(16) float g_h1 [N_NODES * H1F1];
static __device__ __align__(16) float g_es1[N_NODES * 8];
static __device__ __align__(16) float g_ed1[N_NODES * 8];
static __device__ __align__(16) float g_s1 [N_NODES * 8];
static __device__ __align__(16) float g_out1[N_NODES * H1F1];
static __device__ __align__(16) float g_h2 [N_NODES * NCLS];
static __device__ __align__(16) float g_es2[N_NODES];
static __device__ __align__(16) float g_ed2[N_NODES];
static __device__ __align__(16) float g_s2 [N_NODES];
static __device__ int g_is64;

// ---------------- helpers --------------------------------------------------
__device__ __forceinline__ void red_add_v4(float* p, float a, float b, float c, float d) {
    asm volatile("red.global.add.v4.f32 [%0], {%1,%2,%3,%4};"
                 :: "l"(p), "f"(a), "f"(b), "f"(c), "f"(d) : "memory");
}
__device__ __forceinline__ void red_add_f32(float* p, float v) {
    asm volatile("red.global.add.f32 [%0], %1;" :: "l"(p), "f"(v) : "memory");
}
// exp(leaky_relu(a+b)) -- identical code in sum & agg passes so p matches exactly
__device__ __forceinline__ float pexp(float a, float b) {
    float e = a + b;
    e = (e > 0.f) ? e : NEG_SLOPE * e;
    return __expf(e);
}

// ---------------- K_detect: is the adjacency int64 or int32? ----------------
__global__ void k_detect(const long long* __restrict__ adj64) {
    if (blockIdx.x == 0 && threadIdx.x == 0) {
        int ok = 1;
        for (int i = 0; i < 64; i++) {          // 512B read: safe for both dtypes
            long long v = adj64[i];
            if (v < 0 || v >= N_NODES) ok = 0;
        }
        g_is64 = ok;   // int32 data interpreted as int64 almost surely lands out of range
    }
}

// ---------------- K0a: edge indices -> int32, clamped ----------------------
__global__ void k_convert(const void* __restrict__ adjv) {
    int i = blockIdx.x * blockDim.x + threadIdx.x;
    if (i >= N_EDGES) return;
    int s, d;
    if (g_is64) {
        const long long* a = (const long long*)adjv;
        s = (int)a[i]; d = (int)a[i + N_EDGES];
    } else {
        const int* a = (const int*)adjv;
        s = a[i]; d = a[i + N_EDGES];
    }
    s = min(max(s, 0), N_NODES - 1);
    d = min(max(d, 0), N_NODES - 1);
    g_src[i] = s;
    g_dst[i] = d;
}

// ---------------- K0b: zero accumulators ------------------------------------
__global__ void k_zero(float* __restrict__ dout) {
    int i = blockIdx.x * blockDim.x + threadIdx.x;
    if (i < N_NODES * H1F1) g_out1[i] = 0.f;
    if (i < N_NODES * 8)    g_s1[i]   = 0.f;
    if (i < N_NODES)        g_s2[i]   = 0.f;
    if (i < N_NODES * NCLS) dout[i]   = 0.f;
}

// ---------------- K1: h1 = x @ W1 ; es1/ed1 --------------------------------
__global__ __launch_bounds__(256)
void k_gemm1(const float* __restrict__ x, const float* __restrict__ W1,
             const float* __restrict__ a1s, const float* __restrict__ a1d) {
    __shared__ float Wsm[IN_DIM * H1F1];      // 32 KB
    __shared__ float Asm[64], Bsm[64];
    int tid = threadIdx.x;
    for (int t = tid; t < IN_DIM * H1F1; t += 256) Wsm[t] = W1[t];
    if (tid < 64) { Asm[tid] = a1s[tid]; Bsm[tid] = a1d[tid]; }
    __syncthreads();

    int node = blockIdx.x * 256 + tid;
    if (node >= N_NODES) return;

    float acc[H1F1];
#pragma unroll
    for (int j = 0; j < H1F1; j++) acc[j] = 0.f;

    const float4* xrow = (const float4*)(x + (size_t)node * IN_DIM);
#pragma unroll 4
    for (int kk = 0; kk < IN_DIM / 4; kk++) {
        float4 xv = __ldg(xrow + kk);
        float xs4[4] = {xv.x, xv.y, xv.z, xv.w};
#pragma unroll
        for (int u = 0; u < 4; u++) {
            float xs = xs4[u];
            const float4* wr = (const float4*)&Wsm[(kk * 4 + u) * H1F1];
#pragma unroll
            for (int j4 = 0; j4 < 16; j4++) {
                float4 w = wr[j4];
                acc[j4 * 4 + 0] += xs * w.x;
                acc[j4 * 4 + 1] += xs * w.y;
                acc[j4 * 4 + 2] += xs * w.z;
                acc[j4 * 4 + 3] += xs * w.w;
            }
        }
    }
    // write h1 + attention logits
    float4* hout = (float4*)&g_h1[(size_t)node * H1F1];
#pragma unroll
    for (int j4 = 0; j4 < 16; j4++)
        hout[j4] = make_float4(acc[j4*4+0], acc[j4*4+1], acc[j4*4+2], acc[j4*4+3]);

#pragma unroll
    for (int h = 0; h < 8; h++) {
        float es = 0.f, ed = 0.f;
#pragma unroll
        for (int f = 0; f < 8; f++) {
            es += acc[h * 8 + f] * Asm[h * 8 + f];
            ed += acc[h * 8 + f] * Bsm[h * 8 + f];
        }
        g_es1[node * 8 + h] = es;
        g_ed1[node * 8 + h] = ed;
    }
}

// ---------------- K2: layer1 softmax-denominator pass ----------------------
__global__ void k_l1_sum() {
    int i = blockIdx.x * blockDim.x + threadIdx.x;
    if (i >= E_TOT) return;
    int s, d;
    if (i < N_EDGES) { s = g_src[i]; d = g_dst[i]; }
    else             { s = d = i - N_EDGES; }
    float4 es0 = *(const float4*)&g_es1[s * 8];
    float4 es1 = *(const float4*)&g_es1[s * 8 + 4];
    float4 ed0 = *(const float4*)&g_ed1[d * 8];
    float4 ed1 = *(const float4*)&g_ed1[d * 8 + 4];
    red_add_v4(&g_s1[d * 8],
               pexp(es0.x, ed0.x), pexp(es0.y, ed0.y),
               pexp(es0.z, ed0.z), pexp(es0.w, ed0.w));
    red_add_v4(&g_s1[d * 8 + 4],
               pexp(es1.x, ed1.x), pexp(es1.y, ed1.y),
               pexp(es1.z, ed1.z), pexp(es1.w, ed1.w));
}

// ---------------- K3: layer1 aggregate pass --------------------------------
__global__ void k_l1_agg() {
    int i = blockIdx.x * blockDim.x + threadIdx.x;
    if (i >= E_TOT) return;
    int s, d;
    if (i < N_EDGES) { s = g_src[i]; d = g_dst[i]; }
    else             { s = d = i - N_EDGES; }
    float4 es0 = *(const float4*)&g_es1[s * 8];
    float4 es1 = *(const float4*)&g_es1[s * 8 + 4];
    float4 ed0 = *(const float4*)&g_ed1[d * 8];
    float4 ed1 = *(const float4*)&g_ed1[d * 8 + 4];
    float4 sd0 = *(const float4*)&g_s1[d * 8];
    float4 sd1 = *(const float4*)&g_s1[d * 8 + 4];
    float w[8];
    w[0] = pexp(es0.x, ed0.x) / sd0.x;  w[1] = pexp(es0.y, ed0.y) / sd0.y;
    w[2] = pexp(es0.z, ed0.z) / sd0.z;  w[3] = pexp(es0.w, ed0.w) / sd0.w;
    w[4] = pexp(es1.x, ed1.x) / sd1.x;  w[5] = pexp(es1.y, ed1.y) / sd1.y;
    w[6] = pexp(es1.z, ed1.z) / sd1.z;  w[7] = pexp(es1.w, ed1.w) / sd1.w;
    const float4* hs = (const float4*)&g_h1[(size_t)s * H1F1];
    float* ob = &g_out1[(size_t)d * H1F1];
#pragma unroll
    for (int j4 = 0; j4 < 16; j4++) {
        float4 hv = __ldg(hs + j4);
        float wj = w[j4 >> 1];
        red_add_v4(ob + j4 * 4, hv.x * wj, hv.y * wj, hv.z * wj, hv.w * wj);
    }
}

// ---------------- K4: x2 = elu(out1) ; h2 = x2 @ W2 ; es2/ed2 --------------
__global__ __launch_bounds__(256)
void k_gemm2(const float* __restrict__ W2,
             const float* __restrict__ a2s, const float* __restrict__ a2d) {
    __shared__ float Wsm[H1F1 * NCLS];   // 10 KB
    __shared__ float Asm[NCLS], Bsm[NCLS];
    int tid = threadIdx.x;
    for (int t = tid; t < H1F1 * NCLS; t += 256) Wsm[t] = W2[t];
    if (tid < NCLS) { Asm[tid] = a2s[tid]; Bsm[tid] = a2d[tid]; }
    __syncthreads();

    int node = blockIdx.x * 256 + tid;
    if (node >= N_NODES) return;

    float acc[NCLS];
#pragma unroll
    for (int c = 0; c < NCLS; c++) acc[c] = 0.f;

    const float4* xrow = (const float4*)&g_out1[(size_t)node * H1F1];
#pragma unroll 4
    for (int kk = 0; kk < H1F1 / 4; kk++) {
        float4 xv = xrow[kk];
        float xs4[4];
        xs4[0] = xv.x > 0.f ? xv.x : expm1f(xv.x);
        xs4[1] = xv.y > 0.f ? xv.y : expm1f(xv.y);
        xs4[2] = xv.z > 0.f ? xv.z : expm1f(xv.z);
        xs4[3] = xv.w > 0.f ? xv.w : expm1f(xv.w);
#pragma unroll
        for (int u = 0; u < 4; u++) {
            float xs = xs4[u];
            const float4* wr = (const float4*)&Wsm[(kk * 4 + u) * NCLS];
#pragma unroll
            for (int c4 = 0; c4 < NCLS / 4; c4++) {
                float4 w = wr[c4];
                acc[c4 * 4 + 0] += xs * w.x;
                acc[c4 * 4 + 1] += xs * w.y;
                acc[c4 * 4 + 2] += xs * w.z;
                acc[c4 * 4 + 3] += xs * w.w;
            }
        }
    }
    float4* hout = (float4*)&g_h2[(size_t)node * NCLS];
#pragma unroll
    for (int c4 = 0; c4 < NCLS / 4; c4++)
        hout[c4] = make_float4(acc[c4*4+0], acc[c4*4+1], acc[c4*4+2], acc[c4*4+3]);

    float es = 0.f, ed = 0.f;
#pragma unroll
    for (int c = 0; c < NCLS; c++) { es += acc[c] * Asm[c]; ed += acc[c] * Bsm[c]; }
    g_es2[node] = es;
    g_ed2[node] = ed;
}

// ---------------- K5: layer2 denominator -----------------------------------
__global__ void k_l2_sum() {
    int i = blockIdx.x * blockDim.x + threadIdx.x;
    if (i >= E_TOT) return;
    int s, d;
    if (i < N_EDGES) { s = g_src[i]; d = g_dst[i]; }
    else             { s = d = i - N_EDGES; }
    red_add_f32(&g_s2[d], pexp(g_es2[s], g_ed2[d]));
}

// ---------------- K6: layer2 aggregate into d_out ---------------------------
__global__ void k_l2_agg(float* __restrict__ out) {
    int i = blockIdx.x * blockDim.x + threadIdx.x;
    if (i >= E_TOT) return;
    int s, d;
    if (i < N_EDGES) { s = g_src[i]; d = g_dst[i]; }
    else             { s = d = i - N_EDGES; }
    float w = pexp(g_es2[s], g_ed2[d]) / g_s2[d];
    const float4* hs = (const float4*)&g_h2[(size_t)s * NCLS];
    float* ob = out + (size_t)d * NCLS;
#pragma unroll
    for (int c4 = 0; c4 < NCLS / 4; c4++) {
        float4 hv = __ldg(hs + c4);
        red_add_v4(ob + c4 * 4, hv.x * w, hv.y * w, hv.z * w, hv.w * w);
    }
}

// ---------------- K7: in-place log_softmax ----------------------------------
__global__ __launch_bounds__(256)
void k_logsoftmax(float* __restrict__ out) {
    int node = blockIdx.x * 256 + threadIdx.x;
    if (node >= N_NODES) return;
    float v[NCLS];
    float4* row = (float4*)(out + (size_t)node * NCLS);
#pragma unroll
    for (int c4 = 0; c4 < NCLS / 4; c4++) {
        float4 t = row[c4];
        v[c4*4+0] = t.x; v[c4*4+1] = t.y; v[c4*4+2] = t.z; v[c4*4+3] = t.w;
    }
    float m = v[0];
#pragma unroll
    for (int c = 1; c < NCLS; c++) m = fmaxf(m, v[c]);
    float sum = 0.f;
#pragma unroll
    for (int c = 0; c < NCLS; c++) sum += expf(v[c] - m);
    float lse = m + logf(sum);
#pragma unroll
    for (int c4 = 0; c4 < NCLS / 4; c4++)
        row[c4] = make_float4(v[c4*4+0]-lse, v[c4*4+1]-lse, v[c4*4+2]-lse, v[c4*4+3]-lse);
}

// ---------------- launch ----------------------------------------------------
extern "C" void kernel_launch(void* const* d_in, const int* in_sizes, int n_in,
                              void* d_out, int out_size) {
    // Identify inputs by element count (robust to metadata ordering).
    int ix = -1, ia = -1, iw1 = -1, iw2 = -1;
    int p64[2] = {-1, -1}, p40[2] = {-1, -1};
    for (int i = 0; i < n_in; i++) {
        switch (in_sizes[i]) {
            case N_NODES * IN_DIM:   ix  = i; break;   // 12,800,000
            case 2 * N_EDGES:        ia  = i; break;   //  6,400,000
            case IN_DIM * H1F1:      iw1 = i; break;   //      8,192
            case H1F1 * NCLS:        iw2 = i; break;   //      2,560
            case 64: (p64[0] < 0 ? p64[0] : p64[1]) = i; break;
            case 40: (p40[0] < 0 ? p40[0] : p40[1]) = i; break;
        }
    }
    // Insertion order => src before dst. Alphabetical order (W1 first) => dst before src.
    bool alpha = (n_in > 0 && in_sizes[0] == IN_DIM * H1F1);
    int ia1s = alpha ? p64[1] : p64[0], ia1d = alpha ? p64[0] : p64[1];
    int ia2s = alpha ? p40[1] : p40[0], ia2d = alpha ? p40[0] : p40[1];

    const float* x   = (const float*)d_in[ix];
    const void*  adj = d_in[ia];
    const float* W1  = (const float*)d_in[iw1];
    const float* a1s = (const float*)d_in[ia1s];
    const float* a1d = (const float*)d_in[ia1d];
    const float* W2  = (const float*)d_in[iw2];
    const float* a2s = (const float*)d_in[ia2s];
    const float* a2d = (const float*)d_in[ia2d];
    float* out = (float*)d_out;

    const int TB = 256;
    int nodeBlocks = (N_NODES + TB - 1) / TB;
    int edgeBlocks = (E_TOT + TB - 1) / TB;

    k_detect<<<1, 32>>>((const long long*)adj);
    k_convert<<<(N_EDGES + TB - 1) / TB, TB>>>(adj);
    k_zero<<<(N_NODES * H1F1 + TB - 1) / TB, TB>>>(out);
    k_gemm1<<<nodeBlocks, TB>>>(x, W1, a1s, a1d);
    k_l1_sum<<<edgeBlocks, TB>>>();
    k_l1_agg<<<edgeBlocks, TB>>>();
    k_gemm2<<<nodeBlocks, TB>>>(W2, a2s, a2d);
    k_l2_sum<<<edgeBlocks, TB>>>();
    k_l2_agg<<<edgeBlocks, TB>>>(out);
    k_logsoftmax<<<nodeBlocks, TB>>>(out);
}

// round 5
// speedup vs baseline: 1.3962x; 1.3962x over previous
#include <cuda_runtime.h>
#include <cuda_bf16.h>

#define N_NODES  100000
#define N_EDGES  3200000
#define E_TOT    (N_EDGES + N_NODES)   // edges + self loops
#define IN_DIM   128
#define H1F1     64                    // 8 heads x 8 feats
#define NCLS     40
#define NEG_SLOPE 0.2f

// ---------------- scratch (static device globals; 16B-aligned) -------------
static __device__ __align__(16) int   g_src[N_EDGES];
static __device__ __align__(16) int   g_dst[N_EDGES];
static __device__ __align__(16) float g_h1 [N_NODES * H1F1];
static __device__ __align__(16) float g_es1[N_NODES * 8];
static __device__ __align__(16) float g_ed1[N_NODES * 8];
static __device__ __align__(16) float g_s1 [N_NODES * 8];
static __device__ __align__(16) float g_out1[N_NODES * H1F1];
static __device__ __align__(16) float g_h2 [N_NODES * NCLS];
static __device__ __align__(16) float g_es2[N_NODES];
static __device__ __align__(16) float g_ed2[N_NODES];
static __device__ __align__(16) float g_s2 [N_NODES];
static __device__ int g_is64;

// ---------------- helpers --------------------------------------------------
__device__ __forceinline__ void red_add_v4(float* p, float a, float b, float c, float d) {
    asm volatile("red.global.add.v4.f32 [%0], {%1,%2,%3,%4};"
                 :: "l"(p), "f"(a), "f"(b), "f"(c), "f"(d) : "memory");
}
__device__ __forceinline__ void red_add_v2(float* p, float a, float b) {
    asm volatile("red.global.add.v2.f32 [%0], {%1,%2};"
                 :: "l"(p), "f"(a), "f"(b) : "memory");
}
__device__ __forceinline__ void red_add_f32(float* p, float v) {
    asm volatile("red.global.add.f32 [%0], %1;" :: "l"(p), "f"(v) : "memory");
}
// exp(leaky_relu(a+b))
__device__ __forceinline__ float pexp(float a, float b) {
    float e = a + b;
    e = (e > 0.f) ? e : NEG_SLOPE * e;
    return __expf(e);
}

// ---------------- K_detect: adjacency int64 or int32? ----------------------
__global__ void k_detect(const long long* __restrict__ adj64) {
    if (blockIdx.x == 0 && threadIdx.x == 0) {
        int ok = 1;
        for (int i = 0; i < 64; i++) {
            long long v = adj64[i];
            if (v < 0 || v >= N_NODES) ok = 0;
        }
        g_is64 = ok;
    }
}

// ---------------- K0a: edge indices -> int32, clamped ----------------------
__global__ void k_convert(const void* __restrict__ adjv) {
    int i = blockIdx.x * blockDim.x + threadIdx.x;
    if (i >= N_EDGES) return;
    int s, d;
    if (g_is64) {
        const long long* a = (const long long*)adjv;
        s = (int)a[i]; d = (int)a[i + N_EDGES];
    } else {
        const int* a = (const int*)adjv;
        s = a[i]; d = a[i + N_EDGES];
    }
    g_src[i] = min(max(s, 0), N_NODES - 1);
    g_dst[i] = min(max(d, 0), N_NODES - 1);
}

// ---------------- K0b: zero accumulators ------------------------------------
__global__ void k_zero(float* __restrict__ dout) {
    int i = blockIdx.x * blockDim.x + threadIdx.x;
    if (i < N_NODES * H1F1) g_out1[i] = 0.f;
    if (i < N_NODES * 8)    g_s1[i]   = 0.f;
    if (i < N_NODES)        g_s2[i]   = 0.f;
    if (i < N_NODES * NCLS) dout[i]   = 0.f;
}

// ---------------- K1: h1 = x @ W1 ; es1/ed1  (2 threads per node) ----------
__global__ __launch_bounds__(256)
void k_gemm1(const float* __restrict__ x, const float* __restrict__ W1,
             const float* __restrict__ a1s, const float* __restrict__ a1d) {
    __shared__ float Wsm[IN_DIM * H1F1];      // 32 KB, layout [k][64]
    __shared__ float Asm[64], Bsm[64];
    int tid = threadIdx.x;
    for (int t = tid; t < IN_DIM * H1F1; t += 256) Wsm[t] = W1[t];
    if (tid < 64) { Asm[tid] = a1s[tid]; Bsm[tid] = a1d[tid]; }
    __syncthreads();

    int idx  = blockIdx.x * 256 + tid;
    int node = idx >> 1;
    int half = idx & 1;            // this thread computes feats [half*32, half*32+32)
    if (node >= N_NODES) return;

    float acc[32];
#pragma unroll
    for (int j = 0; j < 32; j++) acc[j] = 0.f;

    const float4* xrow = (const float4*)(x + (size_t)node * IN_DIM);
    int fbase = half * 32;
#pragma unroll 4
    for (int kk = 0; kk < IN_DIM / 4; kk++) {
        float4 xv = __ldg(xrow + kk);
        float xs4[4] = {xv.x, xv.y, xv.z, xv.w};
#pragma unroll
        for (int u = 0; u < 4; u++) {
            float xs = xs4[u];
            const float4* wr = (const float4*)&Wsm[(kk * 4 + u) * H1F1 + fbase];
#pragma unroll
            for (int j4 = 0; j4 < 8; j4++) {
                float4 w = wr[j4];
                acc[j4 * 4 + 0] += xs * w.x;
                acc[j4 * 4 + 1] += xs * w.y;
                acc[j4 * 4 + 2] += xs * w.z;
                acc[j4 * 4 + 3] += xs * w.w;
            }
        }
    }
    float4* hout = (float4*)&g_h1[(size_t)node * H1F1 + fbase];
#pragma unroll
    for (int j4 = 0; j4 < 8; j4++)
        hout[j4] = make_float4(acc[j4*4+0], acc[j4*4+1], acc[j4*4+2], acc[j4*4+3]);

    // heads [half*4, half*4+4)
#pragma unroll
    for (int hh = 0; hh < 4; hh++) {
        int h = half * 4 + hh;
        float es = 0.f, ed = 0.f;
#pragma unroll
        for (int f = 0; f < 8; f++) {
            es += acc[hh * 8 + f] * Asm[h * 8 + f];
            ed += acc[hh * 8 + f] * Bsm[h * 8 + f];
        }
        g_es1[node * 8 + h] = es;
        g_ed1[node * 8 + h] = ed;
    }
}

// ---------------- K2: layer1 fused scatter (4 threads per edge) -------------
// Scatters UNNORMALIZED p into s1 and p*h into out1; normalization happens in
// k_gemm2 (out1/s1 is exact softmax-weighted mean).
__global__ void k_l1() {
    int t = blockIdx.x * blockDim.x + threadIdx.x;
    int e = t >> 2, q = t & 3;      // q covers heads [2q,2q+2), feats [16q,16q+16)
    if (e >= E_TOT) return;
    int s, d;
    if (e < N_EDGES) { s = g_src[e]; d = g_dst[e]; }
    else             { s = d = e - N_EDGES; }
    float2 es = *(const float2*)&g_es1[s * 8 + q * 2];
    float2 ed = *(const float2*)&g_ed1[d * 8 + q * 2];
    float w0 = pexp(es.x, ed.x);
    float w1 = pexp(es.y, ed.y);
    red_add_v2(&g_s1[d * 8 + q * 2], w0, w1);
    const float4* hs = (const float4*)&g_h1[(size_t)s * H1F1 + q * 16];
    float* ob = &g_out1[(size_t)d * H1F1 + q * 16];
#pragma unroll
    for (int j = 0; j < 4; j++) {
        float4 hv = __ldg(hs + j);
        float wj = (j < 2) ? w0 : w1;
        red_add_v4(ob + j * 4, hv.x * wj, hv.y * wj, hv.z * wj, hv.w * wj);
    }
}

// ---------------- K3: x2 = elu(out1/s1) ; h2 = x2 @ W2 ; es2/ed2 ------------
__global__ __launch_bounds__(256)
void k_gemm2(const float* __restrict__ W2,
             const float* __restrict__ a2s, const float* __restrict__ a2d) {
    __shared__ float Wsm[H1F1 * NCLS];   // 10 KB
    __shared__ float Asm[NCLS], Bsm[NCLS];
    int tid = threadIdx.x;
    for (int t = tid; t < H1F1 * NCLS; t += 256) Wsm[t] = W2[t];
    if (tid < NCLS) { Asm[tid] = a2s[tid]; Bsm[tid] = a2d[tid]; }
    __syncthreads();

    int node = blockIdx.x * 256 + tid;
    if (node >= N_NODES) return;

    float acc[NCLS];
#pragma unroll
    for (int c = 0; c < NCLS; c++) acc[c] = 0.f;

    // per-head normalization factors
    float4 sa = *(const float4*)&g_s1[node * 8];
    float4 sb = *(const float4*)&g_s1[node * 8 + 4];
    float r[8] = {1.f/sa.x, 1.f/sa.y, 1.f/sa.z, 1.f/sa.w,
                  1.f/sb.x, 1.f/sb.y, 1.f/sb.z, 1.f/sb.w};

    const float4* xrow = (const float4*)&g_out1[(size_t)node * H1F1];
#pragma unroll 4
    for (int kk = 0; kk < H1F1 / 4; kk++) {
        float4 xv = xrow[kk];
        float rh = r[kk >> 1];             // head = (kk*4)/8
        float xs4[4];
        float v0 = xv.x * rh, v1 = xv.y * rh, v2 = xv.z * rh, v3 = xv.w * rh;
        xs4[0] = v0 > 0.f ? v0 : expm1f(v0);
        xs4[1] = v1 > 0.f ? v1 : expm1f(v1);
        xs4[2] = v2 > 0.f ? v2 : expm1f(v2);
        xs4[3] = v3 > 0.f ? v3 : expm1f(v3);
#pragma unroll
        for (int u = 0; u < 4; u++) {
            float xs = xs4[u];
            const float4* wr = (const float4*)&Wsm[(kk * 4 + u) * NCLS];
#pragma unroll
            for (int c4 = 0; c4 < NCLS / 4; c4++) {
                float4 w = wr[c4];
                acc[c4 * 4 + 0] += xs * w.x;
                acc[c4 * 4 + 1] += xs * w.y;
                acc[c4 * 4 + 2] += xs * w.z;
                acc[c4 * 4 + 3] += xs * w.w;
            }
        }
    }
    float4* hout = (float4*)&g_h2[(size_t)node * NCLS];
#pragma unroll
    for (int c4 = 0; c4 < NCLS / 4; c4++)
        hout[c4] = make_float4(acc[c4*4+0], acc[c4*4+1], acc[c4*4+2], acc[c4*4+3]);

    float es = 0.f, ed = 0.f;
#pragma unroll
    for (int c = 0; c < NCLS; c++) { es += acc[c] * Asm[c]; ed += acc[c] * Bsm[c]; }
    g_es2[node] = es;
    g_ed2[node] = ed;
}

// ---------------- K4: layer2 fused scatter (2 threads per edge) -------------
__global__ void k_l2(float* __restrict__ out) {
    int t = blockIdx.x * blockDim.x + threadIdx.x;
    int e = t >> 1, q = t & 1;         // q covers classes [20q, 20q+20)
    if (e >= E_TOT) return;
    int s, d;
    if (e < N_EDGES) { s = g_src[e]; d = g_dst[e]; }
    else             { s = d = e - N_EDGES; }
    float w = pexp(g_es2[s], g_ed2[d]);
    if (q == 0) red_add_f32(&g_s2[d], w);
    const float4* hs = (const float4*)&g_h2[(size_t)s * NCLS + q * 20];
    float* ob = out + (size_t)d * NCLS + q * 20;
#pragma unroll
    for (int j = 0; j < 5; j++) {
        float4 hv = __ldg(hs + j);
        red_add_v4(ob + j * 4, hv.x * w, hv.y * w, hv.z * w, hv.w * w);
    }
}

// ---------------- K5: normalize + in-place log_softmax ----------------------
__global__ __launch_bounds__(256)
void k_logsoftmax(float* __restrict__ out) {
    int node = blockIdx.x * 256 + threadIdx.x;
    if (node >= N_NODES) return;
    float inv = 1.f / g_s2[node];
    float v[NCLS];
    float4* row = (float4*)(out + (size_t)node * NCLS);
#pragma unroll
    for (int c4 = 0; c4 < NCLS / 4; c4++) {
        float4 t = row[c4];
        v[c4*4+0] = t.x * inv; v[c4*4+1] = t.y * inv;
        v[c4*4+2] = t.z * inv; v[c4*4+3] = t.w * inv;
    }
    float m = v[0];
#pragma unroll
    for (int c = 1; c < NCLS; c++) m = fmaxf(m, v[c]);
    float sum = 0.f;
#pragma unroll
    for (int c = 0; c < NCLS; c++) sum += expf(v[c] - m);
    float lse = m + logf(sum);
#pragma unroll
    for (int c4 = 0; c4 < NCLS / 4; c4++)
        row[c4] = make_float4(v[c4*4+0]-lse, v[c4*4+1]-lse, v[c4*4+2]-lse, v[c4*4+3]-lse);
}

// ---------------- launch ----------------------------------------------------
extern "C" void kernel_launch(void* const* d_in, const int* in_sizes, int n_in,
                              void* d_out, int out_size) {
    // Identify inputs by element count (robust to metadata ordering).
    int ix = -1, ia = -1, iw1 = -1, iw2 = -1;
    int p64[2] = {-1, -1}, p40[2] = {-1, -1};
    for (int i = 0; i < n_in; i++) {
        switch (in_sizes[i]) {
            case N_NODES * IN_DIM:   ix  = i; break;
            case 2 * N_EDGES:        ia  = i; break;
            case IN_DIM * H1F1:      iw1 = i; break;
            case H1F1 * NCLS:        iw2 = i; break;
            case 64: (p64[0] < 0 ? p64[0] : p64[1]) = i; break;
            case 40: (p40[0] < 0 ? p40[0] : p40[1]) = i; break;
        }
    }
    bool alpha = (n_in > 0 && in_sizes[0] == IN_DIM * H1F1);
    int ia1s = alpha ? p64[1] : p64[0], ia1d = alpha ? p64[0] : p64[1];
    int ia2s = alpha ? p40[1] : p40[0], ia2d = alpha ? p40[0] : p40[1];

    const float* x   = (const float*)d_in[ix];
    const void*  adj = d_in[ia];
    const float* W1  = (const float*)d_in[iw1];
    const float* a1s = (const float*)d_in[ia1s];
    const float* a1d = (const float*)d_in[ia1d];
    const float* W2  = (const float*)d_in[iw2];
    const float* a2s = (const float*)d_in[ia2s];
    const float* a2d = (const float*)d_in[ia2d];
    float* out = (float*)d_out;

    const int TB = 256;
    int nodeBlocks = (N_NODES + TB - 1) / TB;

    k_detect<<<1, 32>>>((const long long*)adj);
    k_convert<<<(N_EDGES + TB - 1) / TB, TB>>>(adj);
    k_zero<<<(N_NODES * H1F1 + TB - 1) / TB, TB>>>(out);
    k_gemm1<<<(2 * N_NODES + TB - 1) / TB, TB>>>(x, W1, a1s, a1d);
    k_l1<<<(4 * E_TOT + TB - 1) / TB, TB>>>();
    k_gemm2<<<nodeBlocks, TB>>>(W2, a2s, a2d);
    k_l2<<<(2 * E_TOT + TB - 1) / TB, TB>>>(out);
    k_logsoftmax<<<nodeBlocks, TB>>>(out);
}

// round 6
// speedup vs baseline: 1.8181x; 1.3022x over previous
#include <cuda_runtime.h>
#include <cuda_bf16.h>

#define N_NODES  100000
#define N_EDGES  3200000
#define E_TOT    (N_EDGES + N_NODES)   // edges + self loops
#define IN_DIM   128
#define H1F1     64                    // 8 heads x 8 feats
#define NCLS     40
#define NEG_SLOPE 0.2f

// ---------------- scratch (static device globals; 16B-aligned) -------------
static __device__ __align__(16) int   g_src [N_EDGES];
static __device__ __align__(16) int   g_dst [N_EDGES];
static __device__ __align__(16) int   g_deg [N_NODES];
static __device__ __align__(16) int   g_off [N_NODES + 1];
static __device__ __align__(16) int   g_cur [N_NODES];
static __device__ __align__(16) int   g_eidx[E_TOT];          // src per CSR slot
static __device__ __align__(16) float g_h1 [N_NODES * H1F1];
static __device__ __align__(16) float g_es1[N_NODES * 8];
static __device__ __align__(16) float g_ed1[N_NODES * 8];
static __device__ __align__(16) float g_out1[N_NODES * H1F1]; // normalized layer-1 output
static __device__ __align__(16) float g_h2 [N_NODES * NCLS];
static __device__ __align__(16) float g_es2[N_NODES];
static __device__ __align__(16) float g_ed2[N_NODES];
static __device__ int g_is64;

// exp(leaky_relu(a+b))
__device__ __forceinline__ float pexp(float a, float b) {
    float e = a + b;
    e = (e > 0.f) ? e : NEG_SLOPE * e;
    return __expf(e);
}

// ---------------- K_detect: adjacency int64 or int32? ----------------------
__global__ void k_detect(const long long* __restrict__ adj64) {
    if (blockIdx.x == 0 && threadIdx.x == 0) {
        int ok = 1;
        for (int i = 0; i < 64; i++) {
            long long v = adj64[i];
            if (v < 0 || v >= N_NODES) ok = 0;
        }
        g_is64 = ok;
    }
}

// ---------------- deg init: 1 (self loop) -----------------------------------
__global__ void k_init_deg() {
    int i = blockIdx.x * blockDim.x + threadIdx.x;
    if (i < N_NODES) g_deg[i] = 1;
}

// ---------------- convert indices + degree histogram ------------------------
__global__ void k_convert(const void* __restrict__ adjv) {
    int i = blockIdx.x * blockDim.x + threadIdx.x;
    if (i >= N_EDGES) return;
    int s, d;
    if (g_is64) {
        const long long* a = (const long long*)adjv;
        s = (int)a[i]; d = (int)a[i + N_EDGES];
    } else {
        const int* a = (const int*)adjv;
        s = a[i]; d = a[i + N_EDGES];
    }
    s = min(max(s, 0), N_NODES - 1);
    d = min(max(d, 0), N_NODES - 1);
    g_src[i] = s;
    g_dst[i] = d;
    atomicAdd(&g_deg[d], 1);
}

// ---------------- single-block exclusive scan -> offsets + cursors ----------
__global__ __launch_bounds__(1024)
void k_scan() {
    __shared__ int sh[1024];
    const int NT = 1024, CH = (N_NODES + NT - 1) / NT;   // 98
    int t = threadIdx.x;
    int beg = t * CH, end = min(beg + CH, N_NODES);
    int sum = 0;
    for (int i = beg; i < end; i++) sum += g_deg[i];
    sh[t] = sum;
    __syncthreads();
    for (int off = 1; off < NT; off <<= 1) {
        int v = (t >= off) ? sh[t - off] : 0;
        __syncthreads();
        sh[t] += v;
        __syncthreads();
    }
    int base = (t == 0) ? 0 : sh[t - 1];
    for (int i = beg; i < end; i++) {
        g_off[i] = base; g_cur[i] = base;
        base += g_deg[i];
    }
    if (t == NT - 1) g_off[N_NODES] = base;
}

// ---------------- scatter: fill CSR src lists -------------------------------
__global__ void k_scatter() {
    int e = blockIdx.x * blockDim.x + threadIdx.x;
    if (e >= E_TOT) return;
    int s, d;
    if (e < N_EDGES) { s = g_src[e]; d = g_dst[e]; }
    else             { s = d = e - N_EDGES; }
    int pos = atomicAdd(&g_cur[d], 1);
    g_eidx[pos] = s;
}

// ---------------- K1: h1 = x @ W1 ; es1/ed1  (1 thread per node) ------------
__global__ __launch_bounds__(128)
void k_gemm1(const float* __restrict__ x, const float* __restrict__ W1,
             const float* __restrict__ a1s, const float* __restrict__ a1d) {
    __shared__ float Wsm[IN_DIM * H1F1];      // 32 KB
    __shared__ float Asm[64], Bsm[64];
    int tid = threadIdx.x;
    {   // load W1 as float4
        const float4* w4 = (const float4*)W1;
        float4* s4 = (float4*)Wsm;
        for (int t = tid; t < IN_DIM * H1F1 / 4; t += 128) s4[t] = w4[t];
        if (tid < 64) { Asm[tid] = a1s[tid]; Bsm[tid] = a1d[tid]; }
    }
    __syncthreads();

    int node = blockIdx.x * 128 + tid;
    if (node >= N_NODES) return;

    float acc[H1F1];
#pragma unroll
    for (int j = 0; j < H1F1; j++) acc[j] = 0.f;

    const float4* xrow = (const float4*)(x + (size_t)node * IN_DIM);
#pragma unroll 4
    for (int kk = 0; kk < IN_DIM / 4; kk++) {
        float4 xv = __ldg(xrow + kk);
        float xs4[4] = {xv.x, xv.y, xv.z, xv.w};
#pragma unroll
        for (int u = 0; u < 4; u++) {
            float xs = xs4[u];
            const float4* wr = (const float4*)&Wsm[(kk * 4 + u) * H1F1];
#pragma unroll
            for (int j4 = 0; j4 < 16; j4++) {
                float4 w = wr[j4];
                acc[j4 * 4 + 0] += xs * w.x;
                acc[j4 * 4 + 1] += xs * w.y;
                acc[j4 * 4 + 2] += xs * w.z;
                acc[j4 * 4 + 3] += xs * w.w;
            }
        }
    }
    float4* hout = (float4*)&g_h1[(size_t)node * H1F1];
#pragma unroll
    for (int j4 = 0; j4 < 16; j4++)
        hout[j4] = make_float4(acc[j4*4+0], acc[j4*4+1], acc[j4*4+2], acc[j4*4+3]);

#pragma unroll
    for (int h = 0; h < 8; h++) {
        float es = 0.f, ed = 0.f;
#pragma unroll
        for (int f = 0; f < 8; f++) {
            es += acc[h * 8 + f] * Asm[h * 8 + f];
            ed += acc[h * 8 + f] * Bsm[h * 8 + f];
        }
        g_es1[node * 8 + h] = es;
        g_ed1[node * 8 + h] = ed;
    }
}

// ---------------- K2: layer1 CSR aggregate (1 warp per dst node) ------------
// acc in registers; writes NORMALIZED out1 once. No atomics.
__global__ __launch_bounds__(256)
void k_l1_csr() {
    int w    = (blockIdx.x * blockDim.x + threadIdx.x) >> 5;
    int lane = threadIdx.x & 31;
    if (w >= N_NODES) return;
    int d = w;
    float ed = __ldg(&g_ed1[d * 8 + (lane >> 2)]);   // lane's head = lane/4
    int beg = g_off[d], end = g_off[d + 1];
    float a0 = 0.f, a1 = 0.f, sw = 0.f;
    for (int j = beg; j < end; j++) {
        int s = g_eidx[j];                            // uniform across warp
        float es = __ldg(&g_es1[s * 8 + (lane >> 2)]);
        float wgt = pexp(es, ed);
        float2 h = *(const float2*)&g_h1[(size_t)s * H1F1 + lane * 2];
        a0 += wgt * h.x;
        a1 += wgt * h.y;
        sw += wgt;
    }
    float inv = 1.f / sw;
    *(float2*)&g_out1[(size_t)d * H1F1 + lane * 2] = make_float2(a0 * inv, a1 * inv);
}

// ---------------- K3: x2 = elu(out1) ; h2 = x2 @ W2 ; es2/ed2 ---------------
__global__ __launch_bounds__(256)
void k_gemm2(const float* __restrict__ W2,
             const float* __restrict__ a2s, const float* __restrict__ a2d) {
    __shared__ float Wsm[H1F1 * NCLS];   // 10 KB
    __shared__ float Asm[NCLS], Bsm[NCLS];
    int tid = threadIdx.x;
    for (int t = tid; t < H1F1 * NCLS; t += 256) Wsm[t] = W2[t];
    if (tid < NCLS) { Asm[tid] = a2s[tid]; Bsm[tid] = a2d[tid]; }
    __syncthreads();

    int node = blockIdx.x * 256 + tid;
    if (node >= N_NODES) return;

    float acc[NCLS];
#pragma unroll
    for (int c = 0; c < NCLS; c++) acc[c] = 0.f;

    const float4* xrow = (const float4*)&g_out1[(size_t)node * H1F1];
#pragma unroll 4
    for (int kk = 0; kk < H1F1 / 4; kk++) {
        float4 xv = xrow[kk];
        float xs4[4];
        xs4[0] = xv.x > 0.f ? xv.x : expm1f(xv.x);
        xs4[1] = xv.y > 0.f ? xv.y : expm1f(xv.y);
        xs4[2] = xv.z > 0.f ? xv.z : expm1f(xv.z);
        xs4[3] = xv.w > 0.f ? xv.w : expm1f(xv.w);
#pragma unroll
        for (int u = 0; u < 4; u++) {
            float xs = xs4[u];
            const float4* wr = (const float4*)&Wsm[(kk * 4 + u) * NCLS];
#pragma unroll
            for (int c4 = 0; c4 < NCLS / 4; c4++) {
                float4 w = wr[c4];
                acc[c4 * 4 + 0] += xs * w.x;
                acc[c4 * 4 + 1] += xs * w.y;
                acc[c4 * 4 + 2] += xs * w.z;
                acc[c4 * 4 + 3] += xs * w.w;
            }
        }
    }
    float4* hout = (float4*)&g_h2[(size_t)node * NCLS];
#pragma unroll
    for (int c4 = 0; c4 < NCLS / 4; c4++)
        hout[c4] = make_float4(acc[c4*4+0], acc[c4*4+1], acc[c4*4+2], acc[c4*4+3]);

    float es = 0.f, ed = 0.f;
#pragma unroll
    for (int c = 0; c < NCLS; c++) { es += acc[c] * Asm[c]; ed += acc[c] * Bsm[c]; }
    g_es2[node] = es;
    g_ed2[node] = ed;
}

// ---------------- K4: layer2 CSR aggregate + fused log_softmax --------------
// 1 warp per dst node; lanes 0..19 each own 2 classes. Writes FINAL output.
__global__ __launch_bounds__(256)
void k_l2_csr(float* __restrict__ out) {
    int w    = (blockIdx.x * blockDim.x + threadIdx.x) >> 5;
    int lane = threadIdx.x & 31;
    if (w >= N_NODES) return;
    int d = w;
    float ed = __ldg(&g_ed2[d]);
    int beg = g_off[d], end = g_off[d + 1];
    float a0 = 0.f, a1 = 0.f, sw = 0.f;
    bool act = lane < NCLS / 2;
    for (int j = beg; j < end; j++) {
        int s = g_eidx[j];
        float es = __ldg(&g_es2[s]);
        float wgt = pexp(es, ed);
        if (act) {
            float2 h = *(const float2*)&g_h2[(size_t)s * NCLS + lane * 2];
            a0 += wgt * h.x;
            a1 += wgt * h.y;
        }
        sw += wgt;
    }
    float inv = 1.f / sw;
    float v0 = a0 * inv, v1 = a1 * inv;
    // warp log_softmax over 40 values (2 per active lane)
    float m = act ? fmaxf(v0, v1) : -1e30f;
#pragma unroll
    for (int o = 16; o; o >>= 1) m = fmaxf(m, __shfl_xor_sync(0xffffffffu, m, o));
    float ssum = act ? (expf(v0 - m) + expf(v1 - m)) : 0.f;
#pragma unroll
    for (int o = 16; o; o >>= 1) ssum += __shfl_xor_sync(0xffffffffu, ssum, o);
    float lse = m + logf(ssum);
    if (act)
        *(float2*)&out[(size_t)d * NCLS + lane * 2] = make_float2(v0 - lse, v1 - lse);
}

// ---------------- launch ----------------------------------------------------
extern "C" void kernel_launch(void* const* d_in, const int* in_sizes, int n_in,
                              void* d_out, int out_size) {
    // Identify inputs by element count (robust to metadata ordering).
    int ix = -1, ia = -1, iw1 = -1, iw2 = -1;
    int p64[2] = {-1, -1}, p40[2] = {-1, -1};
    for (int i = 0; i < n_in; i++) {
        switch (in_sizes[i]) {
            case N_NODES * IN_DIM:   ix  = i; break;
            case 2 * N_EDGES:        ia  = i; break;
            case IN_DIM * H1F1:      iw1 = i; break;
            case H1F1 * NCLS:        iw2 = i; break;
            case 64: (p64[0] < 0 ? p64[0] : p64[1]) = i; break;
            case 40: (p40[0] < 0 ? p40[0] : p40[1]) = i; break;
        }
    }
    bool alpha = (n_in > 0 && in_sizes[0] == IN_DIM * H1F1);
    int ia1s = alpha ? p64[1] : p64[0], ia1d = alpha ? p64[0] : p64[1];
    int ia2s = alpha ? p40[1] : p40[0], ia2d = alpha ? p40[0] : p40[1];

    const float* x   = (const float*)d_in[ix];
    const void*  adj = d_in[ia];
    const float* W1  = (const float*)d_in[iw1];
    const float* a1s = (const float*)d_in[ia1s];
    const float* a1d = (const float*)d_in[ia1d];
    const float* W2  = (const float*)d_in[iw2];
    const float* a2s = (const float*)d_in[ia2s];
    const float* a2d = (const float*)d_in[ia2d];
    float* out = (float*)d_out;

    const int TB = 256;
    int warpBlocks = (N_NODES * 32 + TB - 1) / TB;   // 1 warp per node

    k_detect<<<1, 32>>>((const long long*)adj);
    k_init_deg<<<(N_NODES + TB - 1) / TB, TB>>>();
    k_convert<<<(N_EDGES + TB - 1) / TB, TB>>>(adj);
    k_scan<<<1, 1024>>>();
    k_scatter<<<(E_TOT + TB - 1) / TB, TB>>>();
    k_gemm1<<<(N_NODES + 127) / 128, 128>>>(x, W1, a1s, a1d);
    k_l1_csr<<<warpBlocks, TB>>>();
    k_gemm2<<<(N_NODES + TB - 1) / TB, TB>>>(W2, a2s, a2d);
    k_l2_csr<<<warpBlocks, TB>>>(out);
}

// round 7
// speedup vs baseline: 2.5190x; 1.3855x over previous
#include <cuda_runtime.h>
#include <cuda_bf16.h>

#define N_NODES  100000
#define N_EDGES  3200000
#define E_TOT    (N_EDGES + N_NODES)   // edges + self loops
#define IN_DIM   128
#define H1F1     64                    // 8 heads x 8 feats
#define NCLS     40
#define NEG_SLOPE 0.2f
#define SCAN_TB  256
#define SCAN_NB  ((N_NODES + SCAN_TB - 1) / SCAN_TB)   // 391

// ---------------- scratch (static device globals; 16B-aligned) -------------
static __device__ __align__(16) int   g_src [N_EDGES];
static __device__ __align__(16) int   g_dst [N_EDGES];
static __device__ __align__(16) int   g_deg [N_NODES];
static __device__ __align__(16) int   g_off [N_NODES + 1];
static __device__ __align__(16) int   g_cur [N_NODES];
static __device__ __align__(16) int   g_bsum [SCAN_NB];
static __device__ __align__(16) int   g_bbase[SCAN_NB];
static __device__ __align__(16) int   g_eidx[E_TOT];          // src per CSR slot
static __device__ __align__(16) float g_h1 [N_NODES * H1F1];
static __device__ __align__(16) float g_es1[N_NODES * 8];
static __device__ __align__(16) float g_ed1[N_NODES * 8];
static __device__ __align__(16) float g_out1[N_NODES * H1F1]; // normalized layer-1 output
static __device__ __align__(16) float g_h2 [N_NODES * NCLS];
static __device__ __align__(16) float g_es2[N_NODES];
static __device__ __align__(16) float g_ed2[N_NODES];
static __device__ int g_is64;

// exp(leaky_relu(a+b))
__device__ __forceinline__ float pexp(float a, float b) {
    float e = a + b;
    e = (e > 0.f) ? e : NEG_SLOPE * e;
    return __expf(e);
}

// ---------------- K_detect: adjacency int64 or int32? ----------------------
__global__ void k_detect(const long long* __restrict__ adj64) {
    if (blockIdx.x == 0 && threadIdx.x == 0) {
        int ok = 1;
        for (int i = 0; i < 64; i++) {
            long long v = adj64[i];
            if (v < 0 || v >= N_NODES) ok = 0;
        }
        g_is64 = ok;
    }
}

// ---------------- deg init: 1 (self loop) -----------------------------------
__global__ void k_init_deg() {
    int i = blockIdx.x * blockDim.x + threadIdx.x;
    if (i < N_NODES) g_deg[i] = 1;
}

// ---------------- convert indices + degree histogram ------------------------
__global__ void k_convert(const void* __restrict__ adjv) {
    int i = blockIdx.x * blockDim.x + threadIdx.x;
    if (i >= N_EDGES) return;
    int s, d;
    if (g_is64) {
        const long long* a = (const long long*)adjv;
        s = (int)a[i]; d = (int)a[i + N_EDGES];
    } else {
        const int* a = (const int*)adjv;
        s = a[i]; d = a[i + N_EDGES];
    }
    s = min(max(s, 0), N_NODES - 1);
    d = min(max(d, 0), N_NODES - 1);
    g_src[i] = s;
    g_dst[i] = d;
    atomicAdd(&g_deg[d], 1);
}

// ---------------- 3-phase grid scan -----------------------------------------
__global__ __launch_bounds__(SCAN_TB)
void k_scan_local() {             // per-block exclusive scan + block sums
    __shared__ int sh[SCAN_TB];
    int b = blockIdx.x, t = threadIdx.x;
    int i = b * SCAN_TB + t;
    int v = (i < N_NODES) ? g_deg[i] : 0;
    sh[t] = v;
    __syncthreads();
#pragma unroll
    for (int off = 1; off < SCAN_TB; off <<= 1) {
        int u = (t >= off) ? sh[t - off] : 0;
        __syncthreads();
        sh[t] += u;
        __syncthreads();
    }
    if (i < N_NODES) g_off[i] = sh[t] - v;      // exclusive within block
    if (t == SCAN_TB - 1) g_bsum[b] = sh[t];
}

__global__ __launch_bounds__(512)
void k_scan_base() {              // scan 391 block sums (1 block)
    __shared__ int sh[512];
    int t = threadIdx.x;
    int v = (t < SCAN_NB) ? g_bsum[t] : 0;
    sh[t] = v;
    __syncthreads();
#pragma unroll
    for (int off = 1; off < 512; off <<= 1) {
        int u = (t >= off) ? sh[t - off] : 0;
        __syncthreads();
        sh[t] += u;
        __syncthreads();
    }
    if (t < SCAN_NB) g_bbase[t] = sh[t] - v;    // exclusive block base
}

__global__ __launch_bounds__(SCAN_TB)
void k_scan_final() {             // add block base; init cursors
    int b = blockIdx.x, t = threadIdx.x;
    int i = b * SCAN_TB + t;
    if (i < N_NODES) {
        int o = g_off[i] + g_bbase[b];
        g_off[i] = o;
        g_cur[i] = o;
    }
    if (i == 0) g_off[N_NODES] = E_TOT;         // total is a constant
}

// ---------------- scatter: fill CSR src lists -------------------------------
__global__ void k_scatter() {
    int e = blockIdx.x * blockDim.x + threadIdx.x;
    if (e >= E_TOT) return;
    int s, d;
    if (e < N_EDGES) { s = g_src[e]; d = g_dst[e]; }
    else             { s = d = e - N_EDGES; }
    int pos = atomicAdd(&g_cur[d], 1);
    g_eidx[pos] = s;
}

// ---------------- K1: h1 = x @ W1 ; es1/ed1  (1 thread per node) ------------
__global__ __launch_bounds__(128)
void k_gemm1(const float* __restrict__ x, const float* __restrict__ W1,
             const float* __restrict__ a1s, const float* __restrict__ a1d) {
    __shared__ float Wsm[IN_DIM * H1F1];      // 32 KB
    __shared__ float Asm[64], Bsm[64];
    int tid = threadIdx.x;
    {   // load W1 as float4
        const float4* w4 = (const float4*)W1;
        float4* s4 = (float4*)Wsm;
        for (int t = tid; t < IN_DIM * H1F1 / 4; t += 128) s4[t] = w4[t];
        if (tid < 64) { Asm[tid] = a1s[tid]; Bsm[tid] = a1d[tid]; }
    }
    __syncthreads();

    int node = blockIdx.x * 128 + tid;
    if (node >= N_NODES) return;

    float acc[H1F1];
#pragma unroll
    for (int j = 0; j < H1F1; j++) acc[j] = 0.f;

    const float4* xrow = (const float4*)(x + (size_t)node * IN_DIM);
#pragma unroll 4
    for (int kk = 0; kk < IN_DIM / 4; kk++) {
        float4 xv = __ldg(xrow + kk);
        float xs4[4] = {xv.x, xv.y, xv.z, xv.w};
#pragma unroll
        for (int u = 0; u < 4; u++) {
            float xs = xs4[u];
            const float4* wr = (const float4*)&Wsm[(kk * 4 + u) * H1F1];
#pragma unroll
            for (int j4 = 0; j4 < 16; j4++) {
                float4 w = wr[j4];
                acc[j4 * 4 + 0] += xs * w.x;
                acc[j4 * 4 + 1] += xs * w.y;
                acc[j4 * 4 + 2] += xs * w.z;
                acc[j4 * 4 + 3] += xs * w.w;
            }
        }
    }
    float4* hout = (float4*)&g_h1[(size_t)node * H1F1];
#pragma unroll
    for (int j4 = 0; j4 < 16; j4++)
        hout[j4] = make_float4(acc[j4*4+0], acc[j4*4+1], acc[j4*4+2], acc[j4*4+3]);

#pragma unroll
    for (int h = 0; h < 8; h++) {
        float es = 0.f, ed = 0.f;
#pragma unroll
        for (int f = 0; f < 8; f++) {
            es += acc[h * 8 + f] * Asm[h * 8 + f];
            ed += acc[h * 8 + f] * Bsm[h * 8 + f];
        }
        g_es1[node * 8 + h] = es;
        g_ed1[node * 8 + h] = ed;
    }
}

// ---------------- K2: layer1 CSR aggregate (1 warp per dst node) ------------
__global__ __launch_bounds__(256)
void k_l1_csr() {
    int w    = (blockIdx.x * blockDim.x + threadIdx.x) >> 5;
    int lane = threadIdx.x & 31;
    if (w >= N_NODES) return;
    int d = w;
    float ed = __ldg(&g_ed1[d * 8 + (lane >> 2)]);   // lane's head = lane/4
    int beg = g_off[d], end = g_off[d + 1];
    float a0 = 0.f, a1 = 0.f, sw = 0.f;
    for (int j = beg; j < end; j++) {
        int s = g_eidx[j];                            // uniform across warp
        float es = __ldg(&g_es1[s * 8 + (lane >> 2)]);
        float wgt = pexp(es, ed);
        float2 h = *(const float2*)&g_h1[(size_t)s * H1F1 + lane * 2];
        a0 += wgt * h.x;
        a1 += wgt * h.y;
        sw += wgt;
    }
    float inv = 1.f / sw;
    *(float2*)&g_out1[(size_t)d * H1F1 + lane * 2] = make_float2(a0 * inv, a1 * inv);
}

// ---------------- K3: x2 = elu(out1) ; h2 = x2 @ W2 ; es2/ed2 ---------------
__global__ __launch_bounds__(256)
void k_gemm2(const float* __restrict__ W2,
             const float* __restrict__ a2s, const float* __restrict__ a2d) {
    __shared__ float Wsm[H1F1 * NCLS];   // 10 KB
    __shared__ float Asm[NCLS], Bsm[NCLS];
    int tid = threadIdx.x;
    for (int t = tid; t < H1F1 * NCLS; t += 256) Wsm[t] = W2[t];
    if (tid < NCLS) { Asm[tid] = a2s[tid]; Bsm[tid] = a2d[tid]; }
    __syncthreads();

    int node = blockIdx.x * 256 + tid;
    if (node >= N_NODES) return;

    float acc[NCLS];
#pragma unroll
    for (int c = 0; c < NCLS; c++) acc[c] = 0.f;

    const float4* xrow = (const float4*)&g_out1[(size_t)node * H1F1];
#pragma unroll 4
    for (int kk = 0; kk < H1F1 / 4; kk++) {
        float4 xv = xrow[kk];
        float xs4[4];
        xs4[0] = xv.x > 0.f ? xv.x : expm1f(xv.x);
        xs4[1] = xv.y > 0.f ? xv.y : expm1f(xv.y);
        xs4[2] = xv.z > 0.f ? xv.z : expm1f(xv.z);
        xs4[3] = xv.w > 0.f ? xv.w : expm1f(xv.w);
#pragma unroll
        for (int u = 0; u < 4; u++) {
            float xs = xs4[u];
            const float4* wr = (const float4*)&Wsm[(kk * 4 + u) * NCLS];
#pragma unroll
            for (int c4 = 0; c4 < NCLS / 4; c4++) {
                float4 w = wr[c4];
                acc[c4 * 4 + 0] += xs * w.x;
                acc[c4 * 4 + 1] += xs * w.y;
                acc[c4 * 4 + 2] += xs * w.z;
                acc[c4 * 4 + 3] += xs * w.w;
            }
        }
    }
    float4* hout = (float4*)&g_h2[(size_t)node * NCLS];
#pragma unroll
    for (int c4 = 0; c4 < NCLS / 4; c4++)
        hout[c4] = make_float4(acc[c4*4+0], acc[c4*4+1], acc[c4*4+2], acc[c4*4+3]);

    float es = 0.f, ed = 0.f;
#pragma unroll
    for (int c = 0; c < NCLS; c++) { es += acc[c] * Asm[c]; ed += acc[c] * Bsm[c]; }
    g_es2[node] = es;
    g_ed2[node] = ed;
}

// ---------------- K4: layer2 CSR aggregate + fused log_softmax --------------
__global__ __launch_bounds__(256)
void k_l2_csr(float* __restrict__ out) {
    int w    = (blockIdx.x * blockDim.x + threadIdx.x) >> 5;
    int lane = threadIdx.x & 31;
    if (w >= N_NODES) return;
    int d = w;
    float ed = __ldg(&g_ed2[d]);
    int beg = g_off[d], end = g_off[d + 1];
    float a0 = 0.f, a1 = 0.f, sw = 0.f;
    bool act = lane < NCLS / 2;
    for (int j = beg; j < end; j++) {
        int s = g_eidx[j];
        float es = __ldg(&g_es2[s]);
        float wgt = pexp(es, ed);
        if (act) {
            float2 h = *(const float2*)&g_h2[(size_t)s * NCLS + lane * 2];
            a0 += wgt * h.x;
            a1 += wgt * h.y;
        }
        sw += wgt;
    }
    float inv = 1.f / sw;
    float v0 = a0 * inv, v1 = a1 * inv;
    float m = act ? fmaxf(v0, v1) : -1e30f;
#pragma unroll
    for (int o = 16; o; o >>= 1) m = fmaxf(m, __shfl_xor_sync(0xffffffffu, m, o));
    float ssum = act ? (expf(v0 - m) + expf(v1 - m)) : 0.f;
#pragma unroll
    for (int o = 16; o; o >>= 1) ssum += __shfl_xor_sync(0xffffffffu, ssum, o);
    float lse = m + logf(ssum);
    if (act)
        *(float2*)&out[(size_t)d * NCLS + lane * 2] = make_float2(v0 - lse, v1 - lse);
}

// ---------------- launch ----------------------------------------------------
extern "C" void kernel_launch(void* const* d_in, const int* in_sizes, int n_in,
                              void* d_out, int out_size) {
    int ix = -1, ia = -1, iw1 = -1, iw2 = -1;
    int p64[2] = {-1, -1}, p40[2] = {-1, -1};
    for (int i = 0; i < n_in; i++) {
        switch (in_sizes[i]) {
            case N_NODES * IN_DIM:   ix  = i; break;
            case 2 * N_EDGES:        ia  = i; break;
            case IN_DIM * H1F1:      iw1 = i; break;
            case H1F1 * NCLS:        iw2 = i; break;
            case 64: (p64[0] < 0 ? p64[0] : p64[1]) = i; break;
            case 40: (p40[0] < 0 ? p40[0] : p40[1]) = i; break;
        }
    }
    bool alpha = (n_in > 0 && in_sizes[0] == IN_DIM * H1F1);
    int ia1s = alpha ? p64[1] : p64[0], ia1d = alpha ? p64[0] : p64[1];
    int ia2s = alpha ? p40[1] : p40[0], ia2d = alpha ? p40[0] : p40[1];

    const float* x   = (const float*)d_in[ix];
    const void*  adj = d_in[ia];
    const float* W1  = (const float*)d_in[iw1];
    const float* a1s = (const float*)d_in[ia1s];
    const float* a1d = (const float*)d_in[ia1d];
    const float* W2  = (const float*)d_in[iw2];
    const float* a2s = (const float*)d_in[ia2s];
    const float* a2d = (const float*)d_in[ia2d];
    float* out = (float*)d_out;

    const int TB = 256;
    int warpBlocks = (N_NODES * 32 + TB - 1) / TB;   // 1 warp per node

    k_detect<<<1, 32>>>((const long long*)adj);
    k_init_deg<<<(N_NODES + TB - 1) / TB, TB>>>();
    k_convert<<<(N_EDGES + TB - 1) / TB, TB>>>(adj);
    k_scan_local<<<SCAN_NB, SCAN_TB>>>();
    k_scan_base<<<1, 512>>>();
    k_scan_final<<<SCAN_NB, SCAN_TB>>>();
    k_scatter<<<(E_TOT + TB - 1) / TB, TB>>>();
    k_gemm1<<<(N_NODES + 127) / 128, 128>>>(x, W1, a1s, a1d);
    k_l1_csr<<<warpBlocks, TB>>>();
    k_gemm2<<<(N_NODES + TB - 1) / TB, TB>>>(W2, a2s, a2d);
    k_l2_csr<<<warpBlocks, TB>>>(out);
}